// round 1
// baseline (speedup 1.0000x reference)
#include <cuda_runtime.h>
#include <math.h>

#define BATCH 64
#define SEQ   1024
#define CDIM  128
#define NEGV  -1e32f

// Scratch for Q, K, V projections (3 x 32 MB). Static device globals (no alloc).
__device__ float g_Q[BATCH * SEQ * CDIM];
__device__ float g_K[BATCH * SEQ * CDIM];
__device__ float g_V[BATCH * SEQ * CDIM];

static __device__ __forceinline__ float4 f4_scale(float4 a, float s) {
    return make_float4(a.x * s, a.y * s, a.z * s, a.w * s);
}
static __device__ __forceinline__ float4 f4_fma(float p, float4 v, float4 acc) {
    acc.x = fmaf(p, v.x, acc.x);
    acc.y = fmaf(p, v.y, acc.y);
    acc.z = fmaf(p, v.z, acc.z);
    acc.w = fmaf(p, v.w, acc.w);
    return acc;
}
static __device__ __forceinline__ float f4_dot_acc(float4 a, float4 b, float acc) {
    acc = fmaf(a.x, b.x, acc);
    acc = fmaf(a.y, b.y, acc);
    acc = fmaf(a.z, b.z, acc);
    acc = fmaf(a.w, b.w, acc);
    return acc;
}

// ============================================================================
// Kernel 1: fused QKV projection.
// out[n][c] = sum_k x[n][k] * W[c][k] + b[c]  for W in {q_w, k_w, v_w}.
// One block = 64 rows of x. X tile and W matrix live in smem (float4, padded
// stride 33 to kill bank conflicts). Thread (ty,tx): rows ty+16i, cols tx+16j.
// ============================================================================
#define QKV_SMEM ((64 + 128) * 33 * 16)

__global__ __launch_bounds__(256, 2)
void qkv_kernel(const float* __restrict__ x,
                const float* __restrict__ qw, const float* __restrict__ qb,
                const float* __restrict__ kw, const float* __restrict__ kb,
                const float* __restrict__ vw, const float* __restrict__ vb)
{
    extern __shared__ float4 smem[];
    float4* sX = smem;             // 64 rows x 33 float4
    float4* sW = smem + 64 * 33;   // 128 rows x 33 float4

    const int tid = threadIdx.x;
    const int tx = tid & 15;
    const int ty = tid >> 4;
    const int row0 = blockIdx.x * 64;

    // Load X tile (64 x 128 floats = 64 x 32 float4)
    const float4* xg = (const float4*)(x + (size_t)row0 * CDIM);
    for (int idx = tid; idx < 64 * 32; idx += 256) {
        int r = idx >> 5, k4 = idx & 31;
        sX[r * 33 + k4] = xg[r * 32 + k4];
    }

    const float* Wt[3] = {qw, kw, vw};
    const float* Bt[3] = {qb, kb, vb};
    float* Ot[3] = {g_Q, g_K, g_V};

    for (int w = 0; w < 3; w++) {
        __syncthreads();  // previous compute done before overwriting sW
        const float4* wg = (const float4*)Wt[w];
        for (int idx = tid; idx < 128 * 32; idx += 256) {
            int r = idx >> 5, k4 = idx & 31;
            sW[r * 33 + k4] = wg[r * 32 + k4];
        }
        __syncthreads();  // sX (first iter) and sW visible

        float bias[8];
        #pragma unroll
        for (int j = 0; j < 8; j++) bias[j] = Bt[w][tx + 16 * j];

        float acc[4][8];
        #pragma unroll
        for (int i = 0; i < 4; i++)
            #pragma unroll
            for (int j = 0; j < 8; j++) acc[i][j] = 0.f;

        #pragma unroll 8
        for (int k4 = 0; k4 < 32; k4++) {
            float4 a[4], bv[8];
            #pragma unroll
            for (int i = 0; i < 4; i++) a[i] = sX[(ty + 16 * i) * 33 + k4];
            #pragma unroll
            for (int j = 0; j < 8; j++) bv[j] = sW[(tx + 16 * j) * 33 + k4];
            #pragma unroll
            for (int i = 0; i < 4; i++)
                #pragma unroll
                for (int j = 0; j < 8; j++)
                    acc[i][j] = f4_dot_acc(a[i], bv[j], acc[i][j]);
        }

        float* O = Ot[w];
        #pragma unroll
        for (int i = 0; i < 4; i++) {
            int r = row0 + ty + 16 * i;
            #pragma unroll
            for (int j = 0; j < 8; j++)
                O[(size_t)r * CDIM + tx + 16 * j] = acc[i][j] + bias[j];
        }
    }
}

// ============================================================================
// Kernel 2: flash-style masked attention.
// Block = (batch b, 64-row q-tile). Online softmax over K tiles of 64 rows,
// skipping tiles entirely past valid_len. Rows >= valid_len output exact 0.
// Thread (ty,tx): S rows ty+16i, S cols tx+16j; O rows ty+16i, O d4 = tx+16j4.
// smem: sQ | (sK aliased with sP) | sV  -> ~99 KB, 2 CTAs/SM.
// ============================================================================
#define ATT_SMEM (3 * 64 * 33 * 16)

__global__ __launch_bounds__(256, 2)
void attn_kernel(const int* __restrict__ valid_lens, float* __restrict__ out)
{
    extern __shared__ float4 smem[];
    float4* sQ  = smem;                 // 64 x 33 f4
    float4* sKP = smem + 64 * 33;       // union: K tile / P tile
    float4* sV  = smem + 2 * 64 * 33;   // 64 x 33 f4
    float*  sP  = (float*)sKP;          // 64 x 65 floats (16.6 KB <= 33 KB)

    const int tid = threadIdx.x;
    const int tx = tid & 15;
    const int ty = tid >> 4;
    const int b  = blockIdx.y;
    const int qt = blockIdx.x;
    const int row0 = qt * 64;
    const int vl = valid_lens[b];

    float* og = out + (size_t)(b * SEQ + row0) * CDIM;

    if (row0 >= vl) {
        // whole tile is masked rows -> exact zeros
        float4* o4 = (float4*)og;
        float4 z = make_float4(0.f, 0.f, 0.f, 0.f);
        for (int idx = tid; idx < 64 * 32; idx += 256) o4[idx] = z;
        return;
    }

    // Load Q tile
    const float4* Qg = (const float4*)(g_Q + (size_t)(b * SEQ + row0) * CDIM);
    for (int idx = tid; idx < 64 * 32; idx += 256) {
        int r = idx >> 5, k4 = idx & 31;
        sQ[r * 33 + k4] = Qg[r * 32 + k4];
    }

    float m[4], l[4];
    float4 o[4][2];
    #pragma unroll
    for (int i = 0; i < 4; i++) {
        m[i] = -INFINITY;
        l[i] = 0.f;
        o[i][0] = make_float4(0.f, 0.f, 0.f, 0.f);
        o[i][1] = make_float4(0.f, 0.f, 0.f, 0.f);
    }

    const int nkt = (vl + 63) >> 6;  // only tiles with a valid column
    for (int kt = 0; kt < nkt; kt++) {
        const float4* Kg = (const float4*)(g_K + (size_t)(b * SEQ + kt * 64) * CDIM);
        const float4* Vg = (const float4*)(g_V + (size_t)(b * SEQ + kt * 64) * CDIM);
        __syncthreads();  // previous PV (reads sP,sV) done; sQ visible (kt=0)
        for (int idx = tid; idx < 64 * 32; idx += 256) {
            int r = idx >> 5, k4 = idx & 31;
            sKP[r * 33 + k4] = Kg[r * 32 + k4];
            sV[r * 33 + k4]  = Vg[r * 32 + k4];
        }
        __syncthreads();  // K, V visible

        // S = Q K^T (4x4 per thread)
        float s[4][4];
        #pragma unroll
        for (int i = 0; i < 4; i++)
            #pragma unroll
            for (int j = 0; j < 4; j++) s[i][j] = 0.f;

        #pragma unroll 8
        for (int k4 = 0; k4 < 32; k4++) {
            float4 a[4], bb[4];
            #pragma unroll
            for (int i = 0; i < 4; i++) a[i] = sQ[(ty + 16 * i) * 33 + k4];
            #pragma unroll
            for (int j = 0; j < 4; j++) bb[j] = sKP[(tx + 16 * j) * 33 + k4];
            #pragma unroll
            for (int i = 0; i < 4; i++)
                #pragma unroll
                for (int j = 0; j < 4; j++)
                    s[i][j] = f4_dot_acc(a[i], bb[j], s[i][j]);
        }

        // mask columns >= vl
        const int cbase = kt * 64;
        #pragma unroll
        for (int j = 0; j < 4; j++) {
            int c = cbase + tx + 16 * j;
            if (c >= vl) {
                #pragma unroll
                for (int i = 0; i < 4; i++) s[i][j] = NEGV;
            }
        }

        // online softmax update
        float mt[4], mn[4], scale[4], rs[4];
        #pragma unroll
        for (int i = 0; i < 4; i++) {
            mt[i] = fmaxf(fmaxf(s[i][0], s[i][1]), fmaxf(s[i][2], s[i][3]));
            #pragma unroll
            for (int off = 1; off < 16; off <<= 1)
                mt[i] = fmaxf(mt[i], __shfl_xor_sync(0xffffffffu, mt[i], off));
            mn[i] = fmaxf(m[i], mt[i]);
            scale[i] = __expf(m[i] - mn[i]);   // first tile: exp(-inf)=0
            m[i] = mn[i];
        }
        #pragma unroll
        for (int i = 0; i < 4; i++) {
            rs[i] = 0.f;
            #pragma unroll
            for (int j = 0; j < 4; j++) {
                s[i][j] = __expf(s[i][j] - mn[i]);   // masked -> exp(-1e32)=0
                rs[i] += s[i][j];
            }
            #pragma unroll
            for (int off = 1; off < 16; off <<= 1)
                rs[i] += __shfl_xor_sync(0xffffffffu, rs[i], off);
            l[i] = l[i] * scale[i] + rs[i];
            o[i][0] = f4_scale(o[i][0], scale[i]);
            o[i][1] = f4_scale(o[i][1], scale[i]);
        }

        __syncthreads();  // everyone done reading sKP as K
        #pragma unroll
        for (int i = 0; i < 4; i++)
            #pragma unroll
            for (int j = 0; j < 4; j++)
                sP[(ty + 16 * i) * 65 + tx + 16 * j] = s[i][j];
        __syncthreads();  // P visible

        // O += P * V
        #pragma unroll 4
        for (int c = 0; c < 64; c++) {
            float p0 = sP[(ty     ) * 65 + c];
            float p1 = sP[(ty + 16) * 65 + c];
            float p2 = sP[(ty + 32) * 65 + c];
            float p3 = sP[(ty + 48) * 65 + c];
            float4 v0 = sV[c * 33 + tx];
            float4 v1 = sV[c * 33 + tx + 16];
            o[0][0] = f4_fma(p0, v0, o[0][0]);  o[0][1] = f4_fma(p0, v1, o[0][1]);
            o[1][0] = f4_fma(p1, v0, o[1][0]);  o[1][1] = f4_fma(p1, v1, o[1][1]);
            o[2][0] = f4_fma(p2, v0, o[2][0]);  o[2][1] = f4_fma(p2, v1, o[2][1]);
            o[3][0] = f4_fma(p3, v0, o[3][0]);  o[3][1] = f4_fma(p3, v1, o[3][1]);
        }
    }

    // epilogue: normalize; zero rows >= vl (reference zeroes masked rows)
    float4* og4 = (float4*)og;
    #pragma unroll
    for (int i = 0; i < 4; i++) {
        int r = ty + 16 * i;
        float inv = (row0 + r < vl) ? (1.f / l[i]) : 0.f;
        og4[r * 32 + tx     ] = f4_scale(o[i][0], inv);
        og4[r * 32 + tx + 16] = f4_scale(o[i][1], inv);
    }
}

// ============================================================================
// Launcher
// ============================================================================
extern "C" void kernel_launch(void* const* d_in, const int* in_sizes, int n_in,
                              void* d_out, int out_size)
{
    const float* x  = (const float*)d_in[0];
    const int*   vl = (const int*)  d_in[1];
    const float* qw = (const float*)d_in[2];
    const float* qb = (const float*)d_in[3];
    const float* kw = (const float*)d_in[4];
    const float* kb = (const float*)d_in[5];
    const float* vw = (const float*)d_in[6];
    const float* vb = (const float*)d_in[7];
    float* out = (float*)d_out;

    cudaFuncSetAttribute(qkv_kernel,  cudaFuncAttributeMaxDynamicSharedMemorySize, QKV_SMEM);
    cudaFuncSetAttribute(attn_kernel, cudaFuncAttributeMaxDynamicSharedMemorySize, ATT_SMEM);

    qkv_kernel<<<(BATCH * SEQ) / 64, 256, QKV_SMEM>>>(x, qw, qb, kw, kb, vw, vb);

    dim3 grid(SEQ / 64, BATCH);
    attn_kernel<<<grid, 256, ATT_SMEM>>>(vl, out);
}